// round 16
// baseline (speedup 1.0000x reference)
#include <cuda_runtime.h>
#include <cuda_fp16.h>
#include <stdint.h>
#include <math.h>

#define NP 512
#define MP 512
#define DD 1024
#define H1C 512
#define H2C 256
#define NPAIR (NP*MP)
#define STRB 80   // bytes per 32-half smem row (64B data + 16B pad)

// Scratch
__device__ uint4  g_h1f[(size_t)16384 * 32 * 32]; // h1 fragment-major (256 MB)
__device__ uint4  g_qf[32 * 64 * 32];             // Q fragment-major (1 MB)
__device__ __half g_w1h[H1C * DD];
__device__ __half g_w2h[H2C * H1C];
__device__ __half g_mh[NP * DD];
__device__ float  g_q2[MP * DD];
__device__ float  g_m2[NP * DD];
__device__ float  g_tq[MP * H1C];                 // Q^2 @ W1^T
__device__ float  g_tm[NP * H1C];                 // M^2 @ W1^T
__device__ float  g_cq[MP], g_cm[NP];
__device__ float  g_dpart[(size_t)NPAIR * 2];
__device__ float  g_cost[NPAIR];

union U4 { uint4 u; __half2 h[4]; };

__device__ __forceinline__ float lrelu(float x){ return x >= 0.f ? x : 0.01f*x; }
__device__ __forceinline__ uint32_t smem_u32(const void* p){
    uint32_t a;
    asm("{ .reg .u64 t; cvta.to.shared.u64 t, %1; cvt.u32.u64 %0, t; }" : "=r"(a) : "l"(p));
    return a;
}
#define CP16(dst, src) asm volatile("cp.async.cg.shared.global [%0], [%1], 16;" :: "r"(dst), "l"(src))
#define CP_COMMIT() asm volatile("cp.async.commit_group;" ::: "memory")
#define CP_WAIT2()  asm volatile("cp.async.wait_group 2;" ::: "memory")

__device__ __forceinline__ void ldmat4(uint32_t* r, uint32_t addr){
    asm volatile("ldmatrix.sync.aligned.m8n8.x4.shared.b16 {%0,%1,%2,%3}, [%4];"
        : "=r"(r[0]),"=r"(r[1]),"=r"(r[2]),"=r"(r[3]) : "r"(addr));
}
__device__ __forceinline__ void mma_f16(float* c, const uint32_t* a, const uint32_t* b){
    asm volatile("mma.sync.aligned.m16n8k16.row.col.f32.f16.f16.f32 "
        "{%0,%1,%2,%3}, {%4,%5,%6,%7}, {%8,%9}, {%0,%1,%2,%3};"
        : "+f"(c[0]),"+f"(c[1]),"+f"(c[2]),"+f"(c[3])
        : "r"(a[0]),"r"(a[1]),"r"(a[2]),"r"(a[3]), "r"(b[0]),"r"(b[1]));
}

// MMA for warp tile 32x64: A-frags in registers, B via LDSM per k-step.
__device__ __forceinline__ void mma_block32(const uint32_t a[2][2][4], uint32_t sb,
        int wn, int rA, int cAd, float acc[2][8][4]){
#pragma unroll
    for (int ks = 0; ks < 2; ks++){
        uint32_t b[8][2];
#pragma unroll
        for (int p = 0; p < 4; p++){
            uint32_t r[4];
            ldmat4(r, sb + (uint32_t)((64*wn + 16*p + rA)*STRB + (2*ks + cAd)*16));
            b[2*p][0] = r[0]; b[2*p+1][0] = r[1];
            b[2*p][1] = r[2]; b[2*p+1][1] = r[3];
        }
#pragma unroll
        for (int mt = 0; mt < 2; mt++)
#pragma unroll
            for (int nt = 0; nt < 8; nt++)
                mma_f16(acc[mt][nt], a[ks][mt], b[nt]);
    }
}

// ---------------------------------------------------------------------------
// Precompute: fp16 weights/M; Q fragment-major; Q^2/M^2 fp32.
// ---------------------------------------------------------------------------
__global__ void k_conv(const float* __restrict__ W1, const float* __restrict__ W2,
                       const float* __restrict__ Q,  const float* __restrict__ Maug){
    const int stride = gridDim.x * blockDim.x;
    const int i0 = blockIdx.x*blockDim.x + threadIdx.x;
    for (int i = i0; i < H1C*DD; i += stride) g_w1h[i] = __float2half(W1[i]);
    for (int i = i0; i < H2C*H1C; i += stride) g_w2h[i] = __float2half(W2[i]);
    for (int i = i0; i < NP*DD;  i += stride){
        g_mh[i] = __float2half(Maug[i]);
        g_m2[i] = Maug[i]*Maug[i];
    }
    for (int i = i0; i < MP*DD;  i += stride) g_q2[i] = Q[i]*Q[i];
    for (int f = i0; f < 32*64*32; f += stride){
        const int t = f >> 11, ks = (f >> 5) & 63, l = f & 31;
        const int r = l >> 2, c = (l & 3) * 2;
        const float* q0 = Q + (size_t)(t*16 + r)     * DD + ks*16;
        const float* q8 = Q + (size_t)(t*16 + r + 8) * DD + ks*16;
        U4 v;
        v.h[0] = __floats2half2_rn(q0[c],   q0[c+1]);
        v.h[1] = __floats2half2_rn(q8[c],   q8[c+1]);
        v.h[2] = __floats2half2_rn(q0[c+8], q0[c+9]);
        v.h[3] = __floats2half2_rn(q8[c+8], q8[c+9]);
        g_qf[f] = v.u;
    }
}

// Row sums of Q^2 / M^2 (exact cost identity)
__global__ void k_rowsum(){
    const int w = (blockIdx.x*blockDim.x + threadIdx.x) >> 5;
    const int lane = threadIdx.x & 31;
    if (w >= MP + NP) return;
    const float* src = (w < MP) ? &g_q2[(size_t)w*DD] : &g_m2[(size_t)(w-MP)*DD];
    float s = 0.f;
    for (int d = lane; d < DD; d += 32) s += src[d];
#pragma unroll
    for (int o = 16; o; o >>= 1) s += __shfl_xor_sync(0xffffffffu, s, o);
    if (lane == 0){ if (w < MP) g_cq[w] = s; else g_cm[w-MP] = s; }
}

// fp32 GEMM 512x512 K=1024, 128x128 tiles (R1-proven shape).
// mode 0: g_tq = g_q2 @ W1^T;  1: g_tm = g_m2 @ W1^T;
//      2: g_cost[n,m] = g_cm[n] + g_cq[m] - 2*(Maug @ Q^T)
__global__ __launch_bounds__(256) void k_gemm512(int mode,
        const float* __restrict__ Wext, const float* __restrict__ Aext,
        const float* __restrict__ Bext){
    __shared__ float As[16][128], Bs[16][128];
    const float *A, *B; float* C;
    if (mode == 0){ A = g_q2; B = Wext; C = g_tq; }
    else if (mode == 1){ A = g_m2; B = Wext; C = g_tm; }
    else { A = Aext; B = Bext; C = g_cost; }

    const int tid = threadIdx.x;
    const int r0 = blockIdx.y*128, c0 = blockIdx.x*128;
    const int tx = tid & 15, ty = tid >> 4;
    float acc[8][8];
#pragma unroll
    for (int i=0;i<8;i++)
#pragma unroll
    for (int j=0;j<8;j++) acc[i][j]=0.f;

    const float4* A4 = (const float4*)A;
    const float4* B4 = (const float4*)B;

    for (int k0 = 0; k0 < DD; k0 += 16){
        const int kq = k0 >> 2;
#pragma unroll
        for (int j = 0; j < 2; j++){
            int idx = tid*2 + j;
            int row = idx >> 2, k4 = idx & 3;
            float4 a = A4[(size_t)(r0+row)*(DD/4) + kq + k4];
            float4 b = B4[(size_t)(c0+row)*(DD/4) + kq + k4];
            int kk = k4*4;
            As[kk+0][row]=a.x; As[kk+1][row]=a.y; As[kk+2][row]=a.z; As[kk+3][row]=a.w;
            Bs[kk+0][row]=b.x; Bs[kk+1][row]=b.y; Bs[kk+2][row]=b.z; Bs[kk+3][row]=b.w;
        }
        __syncthreads();
#pragma unroll
        for (int kk = 0; kk < 16; kk++){
            float av[8], bv[8];
#pragma unroll
            for (int i=0;i<8;i++){ av[i]=As[kk][ty*8+i]; bv[i]=Bs[kk][tx*8+i]; }
#pragma unroll
            for (int i=0;i<8;i++)
#pragma unroll
            for (int j=0;j<8;j++) acc[i][j] = fmaf(av[i], bv[j], acc[i][j]);
        }
        __syncthreads();
    }
#pragma unroll
    for (int i=0;i<8;i++)
#pragma unroll
    for (int j=0;j<8;j++){
        const int r = r0 + ty*8 + i, c = c0 + tx*8 + j;
        float v = acc[i][j];
        if (mode == 2) v = g_cm[r] + g_cq[c] - 2.f*v;
        C[(size_t)r*512 + c] = v;
    }
}

// ---------------------------------------------------------------------------
// Layer 1: acc[m,h] = Q @ (diag(m_n) W1)^T; h1 = lrelu(Tq + Tm + b1 - 2 acc).
// CTA 512 thr, tile 256(m) x 128(h): one n per CTA -> scaled-B amortized 2x.
// 16 warps = 8(wm) x 2(wn), warp tile 32x64.  A = RAW Qf frags (no build).
// Scaled-B: 4-stage ring, LDG(W)+hmul2(M)+STS fill, 2-chunk windows.
// smem: B 4 x 10240 + Mrow 2048 + TmB 512 = 43520
// ---------------------------------------------------------------------------
#define L1_SMEM (4*10240 + 2048 + 512)
#define MOFF    (4*10240)
#define TOFF    (4*10240 + 2048)

__global__ __launch_bounds__(512,1) void k_layer1(const float* __restrict__ b1)
{
    extern __shared__ __align__(16) char smem[];
    const int tid = threadIdx.x, lane = tid & 31, wid = tid >> 5;
    const int h0 = blockIdx.x * 128;          // 4 h-blocks
    const int n  = blockIdx.y >> 1;           // one n per CTA
    const int m0 = (blockIdx.y & 1) * 256;    // half the m range
    const int wm = wid & 7, wn = wid >> 3;
    const int rA = lane & 15, cAd = lane >> 4;

    const uint32_t sbase = smem_u32(smem);

    // M row (fp16) + TmB = Tm[n,h]+b1[h]
    if (tid < 128){
        ((uint4*)(smem + MOFF))[tid] = ((const uint4*)&g_mh[(size_t)n*DD])[tid];
        ((float*)(smem + TOFF))[tid] = g_tm[(size_t)n*H1C + h0 + tid] + b1[h0 + tid];
    }
    __syncthreads();   // M visible to stB

    float acc[2][8][4];
#pragma unroll
    for (int i=0;i<2;i++)
#pragma unroll
    for (int j=0;j<8;j++)
#pragma unroll
    for (int k=0;k<4;k++) acc[i][j][k] = 0.f;

    // B fill: 128 rows x 4 x 16B = 512 uint4; 512 threads -> 1 each
    const int rowB = tid >> 2, chB = tid & 3;
    uint4 rWa, rWb;
    auto ldW = [&](int c) -> uint4 {
        return *(const uint4*)&g_w1h[(size_t)(h0 + rowB)*DD + c*32 + chB*8];
    };
    auto stB = [&](int c, uint4 w){
        U4 msc; msc.u = *(const uint4*)(smem + MOFF + (c*32 + chB*8)*2);
        U4 wi; wi.u = w; U4 o;
#pragma unroll
        for (int i = 0; i < 4; i++) o.h[i] = __hmul2(wi.h[i], msc.h[i]);
        *(uint4*)(smem + (c & 3)*10240 + rowB*STRB + chB*16) = o.u;
    };

    const int qt0 = (m0 + 32*wm) >> 4;   // Qf tile base for this warp

    auto doChunk = [&](int cc){
        uint4 qf[4];
#pragma unroll
        for (int mt = 0; mt < 2; mt++)
#pragma unroll
            for (int ks = 0; ks < 2; ks++)
                qf[mt*2+ks] = g_qf[((qt0 + mt)*64 + (cc*2 + ks))*32 + lane];
        uint32_t afr[2][2][4];
#pragma unroll
        for (int mt = 0; mt < 2; mt++)
#pragma unroll
            for (int ks = 0; ks < 2; ks++){
                afr[ks][mt][0] = qf[mt*2+ks].x; afr[ks][mt][1] = qf[mt*2+ks].y;
                afr[ks][mt][2] = qf[mt*2+ks].z; afr[ks][mt][3] = qf[mt*2+ks].w;
            }
        mma_block32(afr, sbase + (uint32_t)(cc & 3)*10240, wn, rA, cAd, acc);
    };

    // prologue: stages 0,1 filled; W regs hold chunks 2,3
    rWa = ldW(0); rWb = ldW(1);
    stB(0, rWa); stB(1, rWb);
    rWa = ldW(2); rWb = ldW(3);
    __syncthreads();

    for (int c = 0; c < 32; c += 2){
        if (c + 2 < 32) stB(c + 2, rWa);   // stage (c+2)&3: last read 2 windows ago
        if (c + 3 < 32) stB(c + 3, rWb);
        if (c + 4 < 32) rWa = ldW(c + 4);  // LDG latency: 2 chunks of MMA cover
        if (c + 5 < 32) rWb = ldW(c + 5);
        doChunk(c);
        doChunk(c + 1);
        __syncthreads();                   // stB(c+2,c+3) visible next window
    }

    // epilogue: v = Tq[m,h] + TmB[h] - 2*acc; lrelu; store fragment-major
    const int g = lane >> 2;
    const float* tmb = (const float*)(smem + TOFF);
#pragma unroll
    for (int mt = 0; mt < 2; mt++){
        const int mg = m0 + 32*wm + 16*mt + g;
        const size_t rt = (size_t)((n*512 + m0 + 32*wm + 16*mt) >> 4);
#pragma unroll
        for (int ntp = 0; ntp < 4; ntp++){
            const int kstep = (h0 + 64*wn + 16*ntp) >> 4;
            const int col0 = h0 + 64*wn + 16*ntp + 2*(lane&3);
            const float2 tqA0 = *(const float2*)&g_tq[(size_t)mg*H1C + col0];
            const float2 tqB0 = *(const float2*)&g_tq[(size_t)(mg+8)*H1C + col0];
            const float2 tqA8 = *(const float2*)&g_tq[(size_t)mg*H1C + col0 + 8];
            const float2 tqB8 = *(const float2*)&g_tq[(size_t)(mg+8)*H1C + col0 + 8];
            const int cl = col0 - h0;
            const float t0 = tmb[cl],   t1 = tmb[cl+1];
            const float t8 = tmb[cl+8], t9 = tmb[cl+9];
            U4 v;
            v.h[0] = __floats2half2_rn(lrelu(tqA0.x + t0 - 2.f*acc[mt][2*ntp][0]),
                                       lrelu(tqA0.y + t1 - 2.f*acc[mt][2*ntp][1]));
            v.h[1] = __floats2half2_rn(lrelu(tqB0.x + t0 - 2.f*acc[mt][2*ntp][2]),
                                       lrelu(tqB0.y + t1 - 2.f*acc[mt][2*ntp][3]));
            v.h[2] = __floats2half2_rn(lrelu(tqA8.x + t8 - 2.f*acc[mt][2*ntp+1][0]),
                                       lrelu(tqA8.y + t9 - 2.f*acc[mt][2*ntp+1][1]));
            v.h[3] = __floats2half2_rn(lrelu(tqB8.x + t8 - 2.f*acc[mt][2*ntp+1][2]),
                                       lrelu(tqB8.y + t9 - 2.f*acc[mt][2*ntp+1][3]));
            g_h1f[(rt*32 + kstep)*32 + lane] = v.u;
        }
    }
}

// ---------------------------------------------------------------------------
// Layer 2+3 (R12, proven): GEMM [262144 x 256], K=512.  CTA 128x128,
// 2 CTAs/SM.  6-stage cp.async ring, 2-chunk windows.  smem: 61440
// ---------------------------------------------------------------------------
#define L2_SMEM (6*10240)

__global__ __launch_bounds__(256,2) void k_layer2(
    const float* __restrict__ b2, const float* __restrict__ W3)
{
    extern __shared__ __align__(16) char smem[];
    const int tid = threadIdx.x, lane = tid & 31, wid = tid >> 5;
    const int h0 = blockIdx.x * 128;
    const int r0 = blockIdx.y * 128;
    const int wm = wid & 3, wn = wid >> 2;
    const int rA = lane & 15, cAd = lane >> 4;

    const uint32_t sbase = smem_u32(smem);
    const uint32_t sBu = sbase;

    float acc[2][8][4];
#pragma unroll
    for (int i=0;i<2;i++)
#pragma unroll
    for (int j=0;j<8;j++)
#pragma unroll
    for (int k=0;k<4;k++) acc[i][j][k] = 0.f;

    auto fillB = [&](int c){
        const uint32_t s = sBu + (uint32_t)(c % 6) * 10240;
#pragma unroll
        for (int jj = 0; jj < 2; jj++){
            const int idx = tid + 256*jj;
            const int row = idx >> 2, ch = idx & 3;
            CP16(s + (uint32_t)(row*STRB + ch*16),
                 g_w2h + (size_t)(h0 + row)*H1C + c*32 + ch*8);
        }
    };

    const size_t rt0 = (size_t)((r0 + 32*wm) >> 4);

    auto doChunk = [&](int cc){
        uint32_t afr[2][2][4];
#pragma unroll
        for (int mt = 0; mt < 2; mt++)
#pragma unroll
            for (int ks = 0; ks < 2; ks++){
                const uint4 q = g_h1f[((rt0 + mt)*32 + (cc*2 + ks))*32 + lane];
                afr[ks][mt][0] = q.x; afr[ks][mt][1] = q.y;
                afr[ks][mt][2] = q.z; afr[ks][mt][3] = q.w;
            }
        mma_block32(afr, sBu + (uint32_t)(cc % 6)*10240, wn, rA, cAd, acc);
    };

    fillB(0); CP_COMMIT();
    fillB(1); CP_COMMIT();
    fillB(2); CP_COMMIT();
    fillB(3); CP_COMMIT();

    for (int c = 0; c < 16; c += 2){
        CP_WAIT2(); __syncthreads();
        if (c + 4 < 16) fillB(c + 4);
        CP_COMMIT();
        if (c + 5 < 16) fillB(c + 5);
        CP_COMMIT();
        doChunk(c);
        doChunk(c + 1);
    }

    // epilogue: bias + lrelu + W3 dot
    const int g = lane >> 2, tg = lane & 3;
    float dot[2][2];
#pragma unroll
    for (int mt=0; mt<2; mt++){ dot[mt][0]=0.f; dot[mt][1]=0.f; }
#pragma unroll
    for (int nt = 0; nt < 8; nt++){
        const int col = h0 + 64*wn + 8*nt + 2*tg;
        const float b0v = b2[col], b1v = b2[col+1];
        const float w0 = W3[col],  w1 = W3[col+1];
#pragma unroll
        for (int mt = 0; mt < 2; mt++){
            dot[mt][0] += lrelu(acc[mt][nt][0]+b0v)*w0 + lrelu(acc[mt][nt][1]+b1v)*w1;
            dot[mt][1] += lrelu(acc[mt][nt][2]+b0v)*w0 + lrelu(acc[mt][nt][3]+b1v)*w1;
        }
    }
    float* spart = (float*)smem;
    __syncthreads();
#pragma unroll
    for (int mt = 0; mt < 2; mt++)
#pragma unroll
        for (int hh = 0; hh < 2; hh++){
            float v = dot[mt][hh];
            v += __shfl_xor_sync(0xffffffffu, v, 1);
            v += __shfl_xor_sync(0xffffffffu, v, 2);
            if (tg == 0) spart[(32*wm + 16*mt + 8*hh + g)*2 + wn] = v;
        }
    __syncthreads();
    if (tid < 128){
        g_dpart[(size_t)(r0 + tid)*2 + blockIdx.x] = spart[tid*2+0] + spart[tid*2+1];
    }
}

// ---------------------------------------------------------------------------
// Softmax over n (per m) + weighted reductions
// ---------------------------------------------------------------------------
__global__ __launch_bounds__(512) void k_reduce(
    const int* __restrict__ nfg_p, const float* __restrict__ b3,
    float* __restrict__ out)
{
    __shared__ float sm[512];
    const int m = blockIdx.x, n = threadIdx.x;
    const int r = n*MP + m;
    const float v = -(g_dpart[(size_t)r*2] + g_dpart[(size_t)r*2+1] + b3[0]);

    sm[n] = v; __syncthreads();
    for (int s = 256; s; s >>= 1) {
        if (n < s) sm[n] = fmaxf(sm[n], sm[n + s]);
        __syncthreads();
    }
    const float mx = sm[0]; __syncthreads();

    const float p = expf(v - mx);
    sm[n] = p; __syncthreads();
    for (int s = 256; s; s >>= 1) {
        if (n < s) sm[n] += sm[n + s];
        __syncthreads();
    }
    const float Z = sm[0]; __syncthreads();

    const float sval = g_cost[r] * (p / Z);
    sm[n] = sval; __syncthreads();
    for (int s = 256; s; s >>= 1) {
        if (n < s) sm[n] += sm[n + s];
        __syncthreads();
    }
    const float score = sm[0]; __syncthreads();

    const int nfg = *nfg_p;
    sm[n] = (n < nfg) ? sval : 0.f; __syncthreads();
    for (int s = 256; s; s >>= 1) {
        if (n < s) sm[n] += sm[n + s];
        __syncthreads();
    }
    if (n == 0) {
        out[m]      = score;
        out[MP + m] = sm[0];
    }
}

// ---------------------------------------------------------------------------
extern "C" void kernel_launch(void* const* d_in, const int* in_sizes, int n_in,
                              void* d_out, int out_size)
{
    const float* Maug = (const float*)d_in[0];
    const float* Q    = (const float*)d_in[1];
    const float* W1   = (const float*)d_in[2];
    const float* b1   = (const float*)d_in[3];
    const float* W2   = (const float*)d_in[4];
    const float* b2   = (const float*)d_in[5];
    const float* W3   = (const float*)d_in[6];
    const float* b3   = (const float*)d_in[7];
    const int*   nfg  = (const int*)d_in[8];
    float* out = (float*)d_out;

    cudaFuncSetAttribute(k_layer1, cudaFuncAttributeMaxDynamicSharedMemorySize, L1_SMEM);
    cudaFuncSetAttribute(k_layer2, cudaFuncAttributeMaxDynamicSharedMemorySize, L2_SMEM);

    k_conv   <<<512, 256>>>(W1, W2, Q, Maug);
    k_gemm512<<<dim3(4,4), 256>>>(0, W1, nullptr, nullptr);   // Tq
    k_gemm512<<<dim3(4,4), 256>>>(1, W1, nullptr, nullptr);   // Tm
    k_layer1 <<<dim3(4, 1024), 512, L1_SMEM>>>(b1);           // ncu index 3
    k_rowsum <<<128, 256>>>();
    k_gemm512<<<dim3(4,4), 256>>>(2, nullptr, Maug, Q);       // exact cost
    k_layer2 <<<dim3(H2C/128, NPAIR/128), 256, L2_SMEM>>>(b2, W3);
    k_reduce <<<MP, 512>>>(nfg, b3, out);
}

// round 17
// speedup vs baseline: 1.2818x; 1.2818x over previous
#include <cuda_runtime.h>
#include <cuda_fp16.h>
#include <stdint.h>
#include <math.h>

#define NP 512
#define MP 512
#define DD 1024
#define H1C 512
#define H2C 256
#define NPAIR (NP*MP)
#define STRB 80   // bytes per 32-half smem row (64B data + 16B pad)

// Scratch
__device__ uint4  g_h1f[(size_t)16384 * 32 * 32]; // h1 fragment-major (256 MB)
__device__ uint4  g_qf[32 * 64 * 32];             // Q fragment-major (1 MB)
__device__ __half g_w1h[H1C * DD];
__device__ __half g_w2h[H2C * H1C];
__device__ __half g_mh[NP * DD];
__device__ float  g_tq[MP * H1C];                 // Q^2 @ W1^T
__device__ float  g_tm[NP * H1C];                 // M^2 @ W1^T
__device__ float  g_P [NPAIR];                    // Maug @ Q^T
__device__ float  g_cq[MP], g_cm[NP];
__device__ float  g_dpart[(size_t)NPAIR * 2];

union U4 { uint4 u; __half2 h[4]; };

__device__ __forceinline__ float lrelu(float x){ return x >= 0.f ? x : 0.01f*x; }
__device__ __forceinline__ uint32_t smem_u32(const void* p){
    uint32_t a;
    asm("{ .reg .u64 t; cvta.to.shared.u64 t, %1; cvt.u32.u64 %0, t; }" : "=r"(a) : "l"(p));
    return a;
}
#define CP16(dst, src) asm volatile("cp.async.cg.shared.global [%0], [%1], 16;" :: "r"(dst), "l"(src))
#define CP_COMMIT() asm volatile("cp.async.commit_group;" ::: "memory")
#define CP_WAIT2()  asm volatile("cp.async.wait_group 2;" ::: "memory")

__device__ __forceinline__ void ldmat4(uint32_t* r, uint32_t addr){
    asm volatile("ldmatrix.sync.aligned.m8n8.x4.shared.b16 {%0,%1,%2,%3}, [%4];"
        : "=r"(r[0]),"=r"(r[1]),"=r"(r[2]),"=r"(r[3]) : "r"(addr));
}
__device__ __forceinline__ void mma_f16(float* c, const uint32_t* a, const uint32_t* b){
    asm volatile("mma.sync.aligned.m16n8k16.row.col.f32.f16.f16.f32 "
        "{%0,%1,%2,%3}, {%4,%5,%6,%7}, {%8,%9}, {%0,%1,%2,%3};"
        : "+f"(c[0]),"+f"(c[1]),"+f"(c[2]),"+f"(c[3])
        : "r"(a[0]),"r"(a[1]),"r"(a[2]),"r"(a[3]), "r"(b[0]),"r"(b[1]));
}

// MMA for warp tile 32x64: A-frags in registers, B via LDSM per k-step.
__device__ __forceinline__ void mma_block32(const uint32_t a[2][2][4], uint32_t sb,
        int wn, int rA, int cAd, float acc[2][8][4]){
#pragma unroll
    for (int ks = 0; ks < 2; ks++){
        uint32_t b[8][2];
#pragma unroll
        for (int p = 0; p < 4; p++){
            uint32_t r[4];
            ldmat4(r, sb + (uint32_t)((64*wn + 16*p + rA)*STRB + (2*ks + cAd)*16));
            b[2*p][0] = r[0]; b[2*p+1][0] = r[1];
            b[2*p][1] = r[2]; b[2*p+1][1] = r[3];
        }
#pragma unroll
        for (int mt = 0; mt < 2; mt++)
#pragma unroll
            for (int nt = 0; nt < 8; nt++)
                mma_f16(acc[mt][nt], a[ks][mt], b[nt]);
    }
}

// ---------------------------------------------------------------------------
// Precompute: fp16 weights/M; Q fragment-major.
// ---------------------------------------------------------------------------
__global__ void k_conv(const float* __restrict__ W1, const float* __restrict__ W2,
                       const float* __restrict__ Q,  const float* __restrict__ Maug){
    const int stride = gridDim.x * blockDim.x;
    const int i0 = blockIdx.x*blockDim.x + threadIdx.x;
    for (int i = i0; i < H1C*DD; i += stride) g_w1h[i] = __float2half(W1[i]);
    for (int i = i0; i < H2C*H1C; i += stride) g_w2h[i] = __float2half(W2[i]);
    for (int i = i0; i < NP*DD;  i += stride) g_mh[i] = __float2half(Maug[i]);
    for (int f = i0; f < 32*64*32; f += stride){
        const int t = f >> 11, ks = (f >> 5) & 63, l = f & 31;
        const int r = l >> 2, c = (l & 3) * 2;
        const float* q0 = Q + (size_t)(t*16 + r)     * DD + ks*16;
        const float* q8 = Q + (size_t)(t*16 + r + 8) * DD + ks*16;
        U4 v;
        v.h[0] = __floats2half2_rn(q0[c],   q0[c+1]);
        v.h[1] = __floats2half2_rn(q8[c],   q8[c+1]);
        v.h[2] = __floats2half2_rn(q0[c+8], q0[c+9]);
        v.h[3] = __floats2half2_rn(q8[c+8], q8[c+9]);
        g_qf[f] = v.u;
    }
}

// Row sums of Q^2 / M^2 (exact cost identity), from raw inputs.
__global__ void k_rowsum(const float* __restrict__ Q, const float* __restrict__ Maug){
    const int w = (blockIdx.x*blockDim.x + threadIdx.x) >> 5;
    const int lane = threadIdx.x & 31;
    if (w >= MP + NP) return;
    const float* src = (w < MP) ? &Q[(size_t)w*DD] : &Maug[(size_t)(w-MP)*DD];
    float s = 0.f;
    for (int d = lane; d < DD; d += 32){ float t = src[d]; s = fmaf(t, t, s); }
#pragma unroll
    for (int o = 16; o; o >>= 1) s += __shfl_xor_sync(0xffffffffu, s, o);
    if (lane == 0){ if (w < MP) g_cq[w] = s; else g_cm[w-MP] = s; }
}

// One prep kernel, 3 products concurrently (blockIdx.z): 64x64 tiles, K=1024.
// z=0: Tq[m,h]=sum Q[m,d]^2 W1[h,d];  z=1: Tm[n,h]=sum M[n,d]^2 W1[h,d];
// z=2: P[n,m]=sum M[n,d] Q[m,d].  192 CTAs total -> ~1.3 waves.
__global__ __launch_bounds__(256) void k_prep(
        const float* __restrict__ W1, const float* __restrict__ Q,
        const float* __restrict__ Maug){
    __shared__ float As[16][64], Bs[16][64];
    const int z = blockIdx.z;
    const float* A = (z == 0) ? Q : Maug;
    const float* B = (z == 2) ? Q : W1;
    float* C = (z == 0) ? g_tq : (z == 1) ? g_tm : g_P;
    const bool sq = (z < 2);

    const int tid = threadIdx.x;
    const int r0 = blockIdx.y*64, c0 = blockIdx.x*64;
    const int ty = tid >> 4, tx = tid & 15;
    const int lrow = tid >> 2, lk4 = tid & 3;
    float acc[4][4];
#pragma unroll
    for (int i=0;i<4;i++)
#pragma unroll
    for (int j=0;j<4;j++) acc[i][j]=0.f;

    for (int k0 = 0; k0 < DD; k0 += 16){
        float4 a = *(const float4*)&A[(size_t)(r0+lrow)*DD + k0 + lk4*4];
        float4 b = *(const float4*)&B[(size_t)(c0+lrow)*DD + k0 + lk4*4];
        if (sq){ a.x*=a.x; a.y*=a.y; a.z*=a.z; a.w*=a.w; }
        __syncthreads();
        As[lk4*4+0][lrow]=a.x; As[lk4*4+1][lrow]=a.y;
        As[lk4*4+2][lrow]=a.z; As[lk4*4+3][lrow]=a.w;
        Bs[lk4*4+0][lrow]=b.x; Bs[lk4*4+1][lrow]=b.y;
        Bs[lk4*4+2][lrow]=b.z; Bs[lk4*4+3][lrow]=b.w;
        __syncthreads();
#pragma unroll
        for (int k=0;k<16;k++){
            float av[4], bv[4];
#pragma unroll
            for (int i=0;i<4;i++){ av[i]=As[k][ty*4+i]; bv[i]=Bs[k][tx*4+i]; }
#pragma unroll
            for (int i=0;i<4;i++)
#pragma unroll
            for (int j=0;j<4;j++) acc[i][j] = fmaf(av[i], bv[j], acc[i][j]);
        }
    }
#pragma unroll
    for (int i=0;i<4;i++)
#pragma unroll
    for (int j=0;j<4;j++)
        C[(size_t)(r0 + ty*4 + i)*512 + c0 + tx*4 + j] = acc[i][j];
}

// ---------------------------------------------------------------------------
// Layer 1: acc[m,h] = Q @ (diag(m_n) W1)^T; h1 = lrelu(Tq + Tm + b1 - 2 acc).
// CTA 128x128, 256 thr, 2 CTAs/SM (desync).  A = RAW Qf frags (no build).
// Scaled-B: 4-stage ring, LDG(W)+hmul2(M)+STS fill, one barrier per 2 chunks.
// smem: B 4 x 10240 + Mrow 2048 + TmB 512 = 43520
// ---------------------------------------------------------------------------
#define L1_SMEM (4*10240 + 2048 + 512)
#define MOFF    (4*10240)
#define TOFF    (4*10240 + 2048)

__global__ __launch_bounds__(256,2) void k_layer1(const float* __restrict__ b1)
{
    extern __shared__ __align__(16) char smem[];
    const int tid = threadIdx.x, lane = tid & 31, wid = tid >> 5;
    const int h0 = blockIdx.x * 128;          // 4 h-blocks
    const int r0 = blockIdx.y * 128;
    const int n  = r0 >> 9;
    const int m0 = r0 & 511;
    const int wm = wid & 3, wn = wid >> 2;
    const int rA = lane & 15, cAd = lane >> 4;

    const uint32_t sbase = smem_u32(smem);

    // M row (fp16) + TmB = Tm[n,h]+b1[h]
    if (tid < 128){
        ((uint4*)(smem + MOFF))[tid] = ((const uint4*)&g_mh[(size_t)n*DD])[tid];
        ((float*)(smem + TOFF))[tid] = g_tm[(size_t)n*H1C + h0 + tid] + b1[h0 + tid];
    }
    __syncthreads();   // M visible to stB

    float acc[2][8][4];
#pragma unroll
    for (int i=0;i<2;i++)
#pragma unroll
    for (int j=0;j<8;j++)
#pragma unroll
    for (int k=0;k<4;k++) acc[i][j][k] = 0.f;

    // B fill: 128 rows x 4 x 16B = 512 uint4; 256 threads -> 2 each
    const int rowB0 = tid >> 2, rowB1 = 64 + (tid >> 2), chB = tid & 3;
    uint4 rWa0, rWa1, rWb0, rWb1;
    auto ldW = [&](int c, uint4& w0, uint4& w1){
        w0 = *(const uint4*)&g_w1h[(size_t)(h0 + rowB0)*DD + c*32 + chB*8];
        w1 = *(const uint4*)&g_w1h[(size_t)(h0 + rowB1)*DD + c*32 + chB*8];
    };
    auto stB = [&](int c, uint4 w0, uint4 w1){
        U4 msc; msc.u = *(const uint4*)(smem + MOFF + (c*32 + chB*8)*2);
        U4 a, b, o0, o1; a.u = w0; b.u = w1;
#pragma unroll
        for (int i = 0; i < 4; i++){
            o0.h[i] = __hmul2(a.h[i], msc.h[i]);
            o1.h[i] = __hmul2(b.h[i], msc.h[i]);
        }
        *(uint4*)(smem + (c & 3)*10240 + rowB0*STRB + chB*16) = o0.u;
        *(uint4*)(smem + (c & 3)*10240 + rowB1*STRB + chB*16) = o1.u;
    };

    const int qt0 = (m0 + 32*wm) >> 4;   // Qf tile base for this warp

    auto doChunk = [&](int cc){
        uint4 qf[4];
#pragma unroll
        for (int mt = 0; mt < 2; mt++)
#pragma unroll
            for (int ks = 0; ks < 2; ks++)
                qf[mt*2+ks] = g_qf[((qt0 + mt)*64 + (cc*2 + ks))*32 + lane];
        uint32_t afr[2][2][4];
#pragma unroll
        for (int mt = 0; mt < 2; mt++)
#pragma unroll
            for (int ks = 0; ks < 2; ks++){
                afr[ks][mt][0] = qf[mt*2+ks].x; afr[ks][mt][1] = qf[mt*2+ks].y;
                afr[ks][mt][2] = qf[mt*2+ks].z; afr[ks][mt][3] = qf[mt*2+ks].w;
            }
        mma_block32(afr, sbase + (uint32_t)(cc & 3)*10240, wn, rA, cAd, acc);
    };

    // prologue: stages 0,1 filled; W regs hold chunks 2,3
    ldW(0, rWa0, rWa1); stB(0, rWa0, rWa1);
    ldW(1, rWb0, rWb1); stB(1, rWb0, rWb1);
    ldW(2, rWa0, rWa1);
    ldW(3, rWb0, rWb1);
    __syncthreads();

    for (int c = 0; c < 32; c += 2){
        if (c + 2 < 32) stB(c + 2, rWa0, rWa1);  // stage last read 2 windows ago
        if (c + 3 < 32) stB(c + 3, rWb0, rWb1);
        if (c + 4 < 32) ldW(c + 4, rWa0, rWa1);  // latency: 2 chunks of MMA
        if (c + 5 < 32) ldW(c + 5, rWb0, rWb1);
        doChunk(c);
        doChunk(c + 1);
        __syncthreads();                         // stB(c+2,c+3) visible next win
    }

    // epilogue: v = Tq[m,h] + TmB[h] - 2*acc; lrelu; store fragment-major
    const int g = lane >> 2;
    const float* tmb = (const float*)(smem + TOFF);
#pragma unroll
    for (int mt = 0; mt < 2; mt++){
        const int mg = m0 + 32*wm + 16*mt + g;
        const size_t rt = (size_t)((r0 + 32*wm + 16*mt) >> 4);
#pragma unroll
        for (int ntp = 0; ntp < 4; ntp++){
            const int kstep = (h0 + 64*wn + 16*ntp) >> 4;
            const int col0 = h0 + 64*wn + 16*ntp + 2*(lane&3);
            const float2 tqA0 = *(const float2*)&g_tq[(size_t)mg*H1C + col0];
            const float2 tqB0 = *(const float2*)&g_tq[(size_t)(mg+8)*H1C + col0];
            const float2 tqA8 = *(const float2*)&g_tq[(size_t)mg*H1C + col0 + 8];
            const float2 tqB8 = *(const float2*)&g_tq[(size_t)(mg+8)*H1C + col0 + 8];
            const int cl = col0 - h0;
            const float t0 = tmb[cl],   t1 = tmb[cl+1];
            const float t8 = tmb[cl+8], t9 = tmb[cl+9];
            U4 v;
            v.h[0] = __floats2half2_rn(lrelu(tqA0.x + t0 - 2.f*acc[mt][2*ntp][0]),
                                       lrelu(tqA0.y + t1 - 2.f*acc[mt][2*ntp][1]));
            v.h[1] = __floats2half2_rn(lrelu(tqB0.x + t0 - 2.f*acc[mt][2*ntp][2]),
                                       lrelu(tqB0.y + t1 - 2.f*acc[mt][2*ntp][3]));
            v.h[2] = __floats2half2_rn(lrelu(tqA8.x + t8 - 2.f*acc[mt][2*ntp+1][0]),
                                       lrelu(tqA8.y + t9 - 2.f*acc[mt][2*ntp+1][1]));
            v.h[3] = __floats2half2_rn(lrelu(tqB8.x + t8 - 2.f*acc[mt][2*ntp+1][2]),
                                       lrelu(tqB8.y + t9 - 2.f*acc[mt][2*ntp+1][3]));
            g_h1f[(rt*32 + kstep)*32 + lane] = v.u;
        }
    }
}

// ---------------------------------------------------------------------------
// Layer 2+3 (R12, proven): GEMM [262144 x 256], K=512.  CTA 128x128,
// 2 CTAs/SM.  6-stage cp.async ring, 2-chunk windows.  smem: 61440
// ---------------------------------------------------------------------------
#define L2_SMEM (6*10240)

__global__ __launch_bounds__(256,2) void k_layer2(
    const float* __restrict__ b2, const float* __restrict__ W3)
{
    extern __shared__ __align__(16) char smem[];
    const int tid = threadIdx.x, lane = tid & 31, wid = tid >> 5;
    const int h0 = blockIdx.x * 128;
    const int r0 = blockIdx.y * 128;
    const int wm = wid & 3, wn = wid >> 2;
    const int rA = lane & 15, cAd = lane >> 4;

    const uint32_t sbase = smem_u32(smem);
    const uint32_t sBu = sbase;

    float acc[2][8][4];
#pragma unroll
    for (int i=0;i<2;i++)
#pragma unroll
    for (int j=0;j<8;j++)
#pragma unroll
    for (int k=0;k<4;k++) acc[i][j][k] = 0.f;

    auto fillB = [&](int c){
        const uint32_t s = sBu + (uint32_t)(c % 6) * 10240;
#pragma unroll
        for (int jj = 0; jj < 2; jj++){
            const int idx = tid + 256*jj;
            const int row = idx >> 2, ch = idx & 3;
            CP16(s + (uint32_t)(row*STRB + ch*16),
                 g_w2h + (size_t)(h0 + row)*H1C + c*32 + ch*8);
        }
    };

    const size_t rt0 = (size_t)((r0 + 32*wm) >> 4);

    auto doChunk = [&](int cc){
        uint32_t afr[2][2][4];
#pragma unroll
        for (int mt = 0; mt < 2; mt++)
#pragma unroll
            for (int ks = 0; ks < 2; ks++){
                const uint4 q = g_h1f[((rt0 + mt)*32 + (cc*2 + ks))*32 + lane];
                afr[ks][mt][0] = q.x; afr[ks][mt][1] = q.y;
                afr[ks][mt][2] = q.z; afr[ks][mt][3] = q.w;
            }
        mma_block32(afr, sBu + (uint32_t)(cc % 6)*10240, wn, rA, cAd, acc);
    };

    fillB(0); CP_COMMIT();
    fillB(1); CP_COMMIT();
    fillB(2); CP_COMMIT();
    fillB(3); CP_COMMIT();

    for (int c = 0; c < 16; c += 2){
        CP_WAIT2(); __syncthreads();
        if (c + 4 < 16) fillB(c + 4);
        CP_COMMIT();
        if (c + 5 < 16) fillB(c + 5);
        CP_COMMIT();
        doChunk(c);
        doChunk(c + 1);
    }

    // epilogue: bias + lrelu + W3 dot
    const int g = lane >> 2, tg = lane & 3;
    float dot[2][2];
#pragma unroll
    for (int mt=0; mt<2; mt++){ dot[mt][0]=0.f; dot[mt][1]=0.f; }
#pragma unroll
    for (int nt = 0; nt < 8; nt++){
        const int col = h0 + 64*wn + 8*nt + 2*tg;
        const float b0v = b2[col], b1v = b2[col+1];
        const float w0 = W3[col],  w1 = W3[col+1];
#pragma unroll
        for (int mt = 0; mt < 2; mt++){
            dot[mt][0] += lrelu(acc[mt][nt][0]+b0v)*w0 + lrelu(acc[mt][nt][1]+b1v)*w1;
            dot[mt][1] += lrelu(acc[mt][nt][2]+b0v)*w0 + lrelu(acc[mt][nt][3]+b1v)*w1;
        }
    }
    float* spart = (float*)smem;
    __syncthreads();
#pragma unroll
    for (int mt = 0; mt < 2; mt++)
#pragma unroll
        for (int hh = 0; hh < 2; hh++){
            float v = dot[mt][hh];
            v += __shfl_xor_sync(0xffffffffu, v, 1);
            v += __shfl_xor_sync(0xffffffffu, v, 2);
            if (tg == 0) spart[(32*wm + 16*mt + 8*hh + g)*2 + wn] = v;
        }
    __syncthreads();
    if (tid < 128){
        g_dpart[(size_t)(r0 + tid)*2 + blockIdx.x] = spart[tid*2+0] + spart[tid*2+1];
    }
}

// ---------------------------------------------------------------------------
// Softmax over n (per m) + weighted reductions; cost = cm[n]+cq[m]-2P[n,m]
// ---------------------------------------------------------------------------
__global__ __launch_bounds__(512) void k_reduce(
    const int* __restrict__ nfg_p, const float* __restrict__ b3,
    float* __restrict__ out)
{
    __shared__ float sm[512];
    const int m = blockIdx.x, n = threadIdx.x;
    const int r = n*MP + m;
    const float v = -(g_dpart[(size_t)r*2] + g_dpart[(size_t)r*2+1] + b3[0]);

    sm[n] = v; __syncthreads();
    for (int s = 256; s; s >>= 1) {
        if (n < s) sm[n] = fmaxf(sm[n], sm[n + s]);
        __syncthreads();
    }
    const float mx = sm[0]; __syncthreads();

    const float p = expf(v - mx);
    sm[n] = p; __syncthreads();
    for (int s = 256; s; s >>= 1) {
        if (n < s) sm[n] += sm[n + s];
        __syncthreads();
    }
    const float Z = sm[0]; __syncthreads();

    const float cost = g_cm[n] + g_cq[m] - 2.f*g_P[r];
    const float sval = cost * (p / Z);
    sm[n] = sval; __syncthreads();
    for (int s = 256; s; s >>= 1) {
        if (n < s) sm[n] += sm[n + s];
        __syncthreads();
    }
    const float score = sm[0]; __syncthreads();

    const int nfg = *nfg_p;
    sm[n] = (n < nfg) ? sval : 0.f; __syncthreads();
    for (int s = 256; s; s >>= 1) {
        if (n < s) sm[n] += sm[n + s];
        __syncthreads();
    }
    if (n == 0) {
        out[m]      = score;
        out[MP + m] = sm[0];
    }
}

// ---------------------------------------------------------------------------
extern "C" void kernel_launch(void* const* d_in, const int* in_sizes, int n_in,
                              void* d_out, int out_size)
{
    const float* Maug = (const float*)d_in[0];
    const float* Q    = (const float*)d_in[1];
    const float* W1   = (const float*)d_in[2];
    const float* b1   = (const float*)d_in[3];
    const float* W2   = (const float*)d_in[4];
    const float* b2   = (const float*)d_in[5];
    const float* W3   = (const float*)d_in[6];
    const float* b3   = (const float*)d_in[7];
    const int*   nfg  = (const int*)d_in[8];
    float* out = (float*)d_out;

    cudaFuncSetAttribute(k_layer1, cudaFuncAttributeMaxDynamicSharedMemorySize, L1_SMEM);
    cudaFuncSetAttribute(k_layer2, cudaFuncAttributeMaxDynamicSharedMemorySize, L2_SMEM);

    k_conv  <<<512, 256>>>(W1, W2, Q, Maug);
    k_prep  <<<dim3(8,8,3), 256>>>(W1, Q, Maug);   // Tq, Tm, P concurrently
    k_rowsum<<<128, 256>>>(Q, Maug);
    k_layer1<<<dim3(H1C/128, NPAIR/128), 256, L1_SMEM>>>(b1);   // ncu index 3
    k_layer2<<<dim3(H2C/128, NPAIR/128), 256, L2_SMEM>>>(b2, W3);
    k_reduce<<<MP, 512>>>(nfg, b3, out);
}